// round 13
// baseline (speedup 1.0000x reference)
#include <cuda_runtime.h>

// LSTM: B=512, T=1000, IN=39, H=64 (4H=256 gates), OUT=48.
// R13 = R12 + x-projection FMAs moved from the A-window into the B-window.
// R12 profile: A-window is FMA-pipe-saturated (floor 896cyc = 2 warps/SMSP
// x 224 FFMA2 x rt2); non-A window ~1000cyc is latency-bound with the FMA
// pipe idle (fma 43.8% ~= 896/1900). x(t) needs no h, so B-window(t)
// computes xsv = b + W_ih·x(t+1) into 16 regs (x staged 2 steps ahead via a
// 3-buffer ring); A(t+1) = h-part (128 FFMA2, floor 512) + add xsv.
// Numerics identical to R12 (same accumulation order).

#define B_    512
#define T_    1000
#define IN_   39
#define H_    64
#define G_    256
#define OUT_  48
#define ROWS  4
#define CTAS  (B_/ROWS)   // 128
#define KXP   48          // x scalars padded 39->48 (24 pairs, 6 pairs/quarter)

typedef unsigned long long u64;

__device__ __forceinline__ u64 fma2(u64 a, u64 b, u64 c) {
    u64 d;
    asm("fma.rn.f32x2 %0, %1, %2, %3;" : "=l"(d) : "l"(a), "l"(b), "l"(c));
    return d;
}
__device__ __forceinline__ u64 add2(u64 a, u64 b) {
    u64 d;
    asm("add.rn.f32x2 %0, %1, %2;" : "=l"(d) : "l"(a), "l"(b));
    return d;
}
__device__ __forceinline__ u64 pack2(float lo, float hi) {
    u64 d;
    asm("mov.b64 %0, {%1, %2};" : "=l"(d) : "f"(lo), "f"(hi));
    return d;
}
__device__ __forceinline__ void unpack2(u64 v, float &lo, float &hi) {
    asm("mov.b64 {%0, %1}, %2;" : "=f"(lo), "=f"(hi) : "l"(v));
}
__device__ __forceinline__ float sigm(float x) {
    return __fdividef(1.0f, 1.0f + __expf(-x));
}
__device__ __forceinline__ float tanh_(float x) {
    float e = __expf(2.0f * x);
    return 1.0f - __fdividef(2.0f, e + 1.0f);
}

__global__ void __launch_bounds__(256, 1)
lstm_fused(const float* __restrict__ x,
           const float* __restrict__ W_ih,
           const float* __restrict__ W_hh,
           const float* __restrict__ b_ih,
           const float* __restrict__ b_hh,
           const float* __restrict__ W_out,
           const float* __restrict__ b_out,
           float* __restrict__ out)
{
    __shared__ __align__(16) float hsT4[2][H_][4];   // dbl-buf rowpack h, 2KB
    __shared__ __align__(16) float pq[4][4][4][H_];  // [ks][class][row][u] 16KB
    __shared__ __align__(16) u64   pc[2][4][2][OUT_];// dbl-buf head partials 6KB
    __shared__ __align__(16) float woS[H_][OUT_];    // W_out un-dup'd 12KB
    __shared__ __align__(16) float xs[3][ROWS][KXP]; // x tile 3-ring 2.25KB

    const int tid  = threadIdx.x;
    const int row0 = blockIdx.x * ROWS;

    // ---- Phase A identity: (unit ua, k-quarter ks); gates = ua + 64c ----
    const int ua = tid & 63;
    const int ks = tid >> 6;                 // 0..3
    u64 wA[4][16];                           // h-part dup (w,w): 128 regs
    #pragma unroll
    for (int c = 0; c < 4; c++)
        #pragma unroll
        for (int j = 0; j < 16; j++) {
            float v = W_hh[(c*64 + ua)*H_ + ks*16 + j];
            wA[c][j] = pack2(v, v);
        }
    u64 wx[4][6];                            // x-part pair weights: 48 regs
    #pragma unroll
    for (int c = 0; c < 4; c++)
        #pragma unroll
        for (int j = 0; j < 6; j++) {
            int k0 = (ks*6 + j)*2, k1 = k0 + 1;
            float lo = (k0 < IN_) ? W_ih[(c*64 + ua)*IN_ + k0] : 0.0f;
            float hi = (k1 < IN_) ? W_ih[(c*64 + ua)*IN_ + k1] : 0.0f;
            wx[c][j] = pack2(lo, hi);
        }
    const u64 zero2 = pack2(0.0f, 0.0f);
    u64 bias2c[4];                           // (b,0): ks==0 threads only
    #pragma unroll
    for (int c = 0; c < 4; c++) {
        float b = (ks == 0) ? (b_ih[c*64 + ua] + b_hh[c*64 + ua]) : 0.0f;
        bias2c[c] = pack2(b, 0.0f);
    }

    // ---- Phase B identity: (unit ub, row rb) ----
    const int ub = tid & 63;
    const int rb = tid >> 6;
    float cst = 0.0f;

    // ---- stager identity (tid<156): x element (sr, si) ----
    const bool stg = (tid < ROWS*IN_);
    const int  sr  = stg ? (tid / IN_) : 0;
    const int  si  = stg ? (tid % IN_) : 0;

    // ---- head C1 identity (tid>=64): (output o1, k-quarter kc) ----
    const int i1 = tid - 64;                 // 0..191 when tid>=64
    const int o1 = (i1 >= 0) ? (i1 % 48) : 0;
    const int kc = (i1 >= 0) ? (i1 / 48) : 0;
    u64 cb2 = zero2;
    if (i1 >= 0 && kc == 0) { float b = b_out[o1]; cb2 = pack2(b, b); }
    // ---- head C2 identity (tid<48): output o2, all 4 rows ----
    const int o2 = tid;

    // ---- prologue ----
    for (int idx = tid; idx < 3*ROWS*KXP; idx += 256)
        ((float*)xs)[idx] = 0.0f;
    if (tid < H_) {
        #pragma unroll
        for (int r = 0; r < 4; r++) {
            hsT4[0][tid][r] = 0.0f;
            hsT4[1][tid][r] = 0.0f;
        }
    }
    for (int idx = tid; idx < H_*OUT_; idx += 256) {
        int k = idx / OUT_, o = idx % OUT_;
        woS[k][o] = W_out[o*H_ + k];
    }
    __syncthreads();
    if (stg) {
        xs[0][sr][si] = x[((size_t)(row0 + sr) * T_    ) * IN_ + si];
        xs[1][sr][si] = x[((size_t)(row0 + sr) * T_ + 1) * IN_ + si];
    }
    __syncthreads();

    // ---- xsv for t=0 (from xs[0]) ----
    float xsv[4][4];                         // [c][r]
    #pragma unroll
    for (int r = 0; r < 4; r++) {
        u64 axr[4];
        #pragma unroll
        for (int c = 0; c < 4; c++) axr[c] = bias2c[c];
        const ulonglong2* xp = (const ulonglong2*)xs[0][r] + ks*3;
        #pragma unroll
        for (int m = 0; m < 3; m++) {
            ulonglong2 q = xp[m];
            #pragma unroll
            for (int c = 0; c < 4; c++) {
                axr[c] = fma2(wx[c][2*m    ], q.x, axr[c]);
                axr[c] = fma2(wx[c][2*m + 1], q.y, axr[c]);
            }
        }
        #pragma unroll
        for (int c = 0; c < 4; c++) {
            float e, f; unpack2(axr[c], e, f);
            xsv[c][r] = e + f;
        }
    }

    float xnext = 0.0f;
    for (int t = 0; t < T_; t++) {
        const int wb = t & 1;        // B writes hsT4[wb]; C1 writes pc[wb]
        const int hb = wb ^ 1;       // A + C1 read hsT4[hb]; C2 reads pc[hb]
        const bool pf = stg && (t + 2 < T_);
        if (pf) xnext = x[((size_t)(row0 + sr) * T_ + (t + 2)) * IN_ + si];

        // ---- Phase A: h-part only (16 LDS.128 -> 128 FFMA2) + add xsv ----
        {
            u64 a01[4] = {zero2, zero2, zero2, zero2};
            u64 a23[4] = {zero2, zero2, zero2, zero2};
            const ulonglong2* hp = (const ulonglong2*)hsT4[hb] + ks*16;
            #pragma unroll
            for (int j = 0; j < 16; j++) {
                ulonglong2 q = hp[j];        // .x=(r0,r1) .y=(r2,r3)
                #pragma unroll
                for (int c = 0; c < 4; c++) {
                    a01[c] = fma2(wA[c][j], q.x, a01[c]);
                    a23[c] = fma2(wA[c][j], q.y, a23[c]);
                }
            }
            #pragma unroll
            for (int c = 0; c < 4; c++) {
                float v0, v1;
                unpack2(a01[c], v0, v1);
                pq[ks][c][0][ua] = v0 + xsv[c][0];
                pq[ks][c][1][ua] = v1 + xsv[c][1];
                unpack2(a23[c], v0, v1);
                pq[ks][c][2][ua] = v0 + xsv[c][2];
                pq[ks][c][3][ua] = v1 + xsv[c][3];
            }
        }
        __syncthreads();   // bar1

        // ==== B-window: C2(t-2) | B(t) | C1(t-1) | X(t+1) overlapped ====

        // ---- head C2: emit y(t-2) from pc[hb] (tid<48) ----
        if (tid < 48 && t >= 2) {
            u64 s01 = add2(add2(pc[hb][0][0][o2], pc[hb][1][0][o2]),
                           add2(pc[hb][2][0][o2], pc[hb][3][0][o2]));
            u64 s23 = add2(add2(pc[hb][0][1][o2], pc[hb][1][1][o2]),
                           add2(pc[hb][2][1][o2], pc[hb][3][1][o2]));
            float z0, z1, z2, z3;
            unpack2(s01, z0, z1);
            unpack2(s23, z2, z3);
            const size_t tb = (size_t)(t - 2) * OUT_ + o2;
            out[(size_t)(row0    ) * T_ * OUT_ + tb] = sigm(z0);
            out[(size_t)(row0 + 1) * T_ * OUT_ + tb] = sigm(z1);
            out[(size_t)(row0 + 2) * T_ * OUT_ + tb] = sigm(z2);
            out[(size_t)(row0 + 3) * T_ * OUT_ + tb] = sigm(z3);
        }

        // ---- Phase B: sum partials, activations, write h(t) -> hsT4[wb] ----
        {
            float si_ = (pq[0][0][rb][ub] + pq[1][0][rb][ub])
                      + (pq[2][0][rb][ub] + pq[3][0][rb][ub]);
            float sf_ = (pq[0][1][rb][ub] + pq[1][1][rb][ub])
                      + (pq[2][1][rb][ub] + pq[3][1][rb][ub]);
            float sg_ = (pq[0][2][rb][ub] + pq[1][2][rb][ub])
                      + (pq[2][2][rb][ub] + pq[3][2][rb][ub]);
            float so_ = (pq[0][3][rb][ub] + pq[1][3][rb][ub])
                      + (pq[2][3][rb][ub] + pq[3][3][rb][ub]);
            float iv = sigm(si_), fv = sigm(sf_);
            float gv = tanh_(sg_), ov = sigm(so_);
            cst = fv * cst + iv * gv;
            hsT4[wb][ub][rb] = ov * tanh_(cst);
        }

        // ---- head C1: partials of head(h(t-1)) from hsT4[hb] -> pc[wb] ----
        if (i1 >= 0 && t >= 1) {
            u64 a01 = cb2, a23 = cb2;
            const ulonglong2* hp = (const ulonglong2*)hsT4[hb] + kc*16;
            #pragma unroll
            for (int j = 0; j < 16; j++) {
                ulonglong2 q = hp[j];
                float wv = woS[kc*16 + j][o1];
                u64 w2 = pack2(wv, wv);
                a01 = fma2(w2, q.x, a01);
                a23 = fma2(w2, q.y, a23);
            }
            pc[wb][kc][0][o1] = a01;
            pc[wb][kc][1][o1] = a23;
        }

        // ---- X: xsv for step t+1 from xs[(t+1)%3] (fills idle FMA slots) ----
        if (t + 1 < T_) {
            const float (*xcur)[KXP] = xs[(t + 1) % 3];
            #pragma unroll
            for (int r = 0; r < 4; r++) {
                u64 axr[4];
                #pragma unroll
                for (int c = 0; c < 4; c++) axr[c] = bias2c[c];
                const ulonglong2* xp = (const ulonglong2*)xcur[r] + ks*3;
                #pragma unroll
                for (int m = 0; m < 3; m++) {
                    ulonglong2 q = xp[m];
                    #pragma unroll
                    for (int c = 0; c < 4; c++) {
                        axr[c] = fma2(wx[c][2*m    ], q.x, axr[c]);
                        axr[c] = fma2(wx[c][2*m + 1], q.y, axr[c]);
                    }
                }
                #pragma unroll
                for (int c = 0; c < 4; c++) {
                    float e, f; unpack2(axr[c], e, f);
                    xsv[c][r] = e + f;
                }
            }
        }

        if (pf) xs[(t + 2) % 3][sr][si] = xnext;   // publish x(t+2)
        __syncthreads();   // bar2
    }

    // ---- epilogue: head of h(999), then emit y(998), y(999) ----
    if (i1 >= 0) {
        u64 a01 = cb2, a23 = cb2;
        const ulonglong2* hp = (const ulonglong2*)hsT4[1] + kc*16;
        #pragma unroll
        for (int j = 0; j < 16; j++) {
            ulonglong2 q = hp[j];
            float wv = woS[kc*16 + j][o1];
            u64 w2 = pack2(wv, wv);
            a01 = fma2(w2, q.x, a01);
            a23 = fma2(w2, q.y, a23);
        }
        pc[0][kc][0][o1] = a01;
        pc[0][kc][1][o1] = a23;
    }
    __syncthreads();
    if (tid < 48) {
        #pragma unroll
        for (int e = 0; e < 2; e++) {   // e=0: y(998) from pc[1]; e=1: y(999) from pc[0]
            const int pb = 1 - e;
            const int ts = 998 + e;
            u64 s01 = add2(add2(pc[pb][0][0][o2], pc[pb][1][0][o2]),
                           add2(pc[pb][2][0][o2], pc[pb][3][0][o2]));
            u64 s23 = add2(add2(pc[pb][0][1][o2], pc[pb][1][1][o2]),
                           add2(pc[pb][2][1][o2], pc[pb][3][1][o2]));
            float z0, z1, z2, z3;
            unpack2(s01, z0, z1);
            unpack2(s23, z2, z3);
            const size_t tb = (size_t)ts * OUT_ + o2;
            out[(size_t)(row0    ) * T_ * OUT_ + tb] = sigm(z0);
            out[(size_t)(row0 + 1) * T_ * OUT_ + tb] = sigm(z1);
            out[(size_t)(row0 + 2) * T_ * OUT_ + tb] = sigm(z2);
            out[(size_t)(row0 + 3) * T_ * OUT_ + tb] = sigm(z3);
        }
    }
}

extern "C" void kernel_launch(void* const* d_in, const int* in_sizes, int n_in,
                              void* d_out, int out_size)
{
    (void)in_sizes; (void)n_in; (void)out_size;
    const float* x     = (const float*)d_in[0];
    const float* W_ih  = (const float*)d_in[1];
    const float* W_hh  = (const float*)d_in[2];
    const float* b_ih  = (const float*)d_in[3];
    const float* b_hh  = (const float*)d_in[4];
    const float* W_out = (const float*)d_in[5];
    const float* b_out = (const float*)d_in[6];
    float* out = (float*)d_out;

    lstm_fused<<<CTAS, 256>>>(x, W_ih, W_hh, b_ih, b_hh, W_out, b_out, out);
}

// round 14
// speedup vs baseline: 1.1869x; 1.1869x over previous
#include <cuda_runtime.h>

// LSTM: B=512, T=1000, IN=39, H=64 (4H=256 gates), OUT=48.
// R14 = R12 + WARP SPECIALIZATION (R13's x-hoist idea, fixed placement).
// 384 threads:
//  - tid 0-255 (A/B warps): A-window = h-part gates only (128 FFMA2, wA=128
//    regs, wx REMOVED -> ~175 regs, no spill). B-window = B + C2 + x-stage.
//  - tid 256-383 (X/C1 warps): A-window = xg(t+1)=b+W_ih·x(t+1) via dup-w
//    T-layout (39 LDS.128 -> 156 FFMA2; wxd=156 regs lives ONLY here).
//    B-window = output head C1 (k-split 2, 96 threads).
// R13 failed because wx+xsv shared threads with wA (regs 250 -> spill).
// Per-SMSP FMA work/step is invariant (~824cyc); specialization compresses
// the serial non-FMA time around it: B-window ~1000 -> ~400.

#define B_    512
#define T_    1000
#define IN_   39
#define H_    64
#define G_    256
#define OUT_  48
#define ROWS  4
#define CTAS  (B_/ROWS)   // 128
#define NTHR  384

typedef unsigned long long u64;

__device__ __forceinline__ u64 fma2(u64 a, u64 b, u64 c) {
    u64 d;
    asm("fma.rn.f32x2 %0, %1, %2, %3;" : "=l"(d) : "l"(a), "l"(b), "l"(c));
    return d;
}
__device__ __forceinline__ u64 add2(u64 a, u64 b) {
    u64 d;
    asm("add.rn.f32x2 %0, %1, %2;" : "=l"(d) : "l"(a), "l"(b));
    return d;
}
__device__ __forceinline__ u64 pack2(float lo, float hi) {
    u64 d;
    asm("mov.b64 %0, {%1, %2};" : "=l"(d) : "f"(lo), "f"(hi));
    return d;
}
__device__ __forceinline__ void unpack2(u64 v, float &lo, float &hi) {
    asm("mov.b64 {%0, %1}, %2;" : "=f"(lo), "=f"(hi) : "l"(v));
}
__device__ __forceinline__ float sigm(float x) {
    return __fdividef(1.0f, 1.0f + __expf(-x));
}
__device__ __forceinline__ float tanh_(float x) {
    float e = __expf(2.0f * x);
    return 1.0f - __fdividef(2.0f, e + 1.0f);
}

__global__ void __launch_bounds__(NTHR, 1)
lstm_fused(const float* __restrict__ x,
           const float* __restrict__ W_ih,
           const float* __restrict__ W_hh,
           const float* __restrict__ b_ih,
           const float* __restrict__ b_hh,
           const float* __restrict__ W_out,
           const float* __restrict__ b_out,
           float* __restrict__ out)
{
    __shared__ __align__(16) float hsT4[2][H_][4];    // dbl-buf rowpack h, 2KB
    __shared__ __align__(16) float pq[4][4][4][H_];   // h-part partials 16KB
    __shared__ __align__(16) u64   pc[2][2][2][OUT_]; // [buf][kh][rp][o] 3KB
    __shared__ __align__(16) float woS[H_][OUT_];     // W_out 12KB
    __shared__ __align__(16) float xs4[2][IN_][4];    // x transposed dbl-buf 1.25KB
    __shared__ __align__(16) u64   xgS[2][4][2][H_];  // xg dbl-buf [buf][c][rp][u] 8KB

    const int tid  = threadIdx.x;
    const int row0 = blockIdx.x * ROWS;
    const bool isAB = (tid < 256);

    // ======== A/B-warp state ========
    const int ua = tid & 63;
    const int ks = (tid >> 6) & 3;
    u64 wA[4][16];                    // only meaningful for isAB
    if (isAB) {
        #pragma unroll
        for (int c = 0; c < 4; c++)
            #pragma unroll
            for (int j = 0; j < 16; j++) {
                float v = W_hh[(c*64 + ua)*H_ + ks*16 + j];
                wA[c][j] = pack2(v, v);
            }
    }
    const u64 zero2 = pack2(0.0f, 0.0f);
    // B identity: (unit ub=ua, row rb=ks)
    const int ub = ua, rb = ks;
    const int rp = rb >> 1, rl = rb & 1;
    float cst = 0.0f;
    // stager identity (tid<156): x element (sr, si)
    const bool stg = isAB && (tid < ROWS*IN_);
    const int  sr  = stg ? (tid / IN_) : 0;
    const int  si  = stg ? (tid % IN_) : 0;
    // C2 identity (tid<48): output o2
    const int o2 = tid;

    // ======== X/C1-warp state ========
    const int gx = tid - 256;         // 0..127 when valid
    const int xu = (gx >= 0) ? (gx & 63) : 0;
    const int xc = (gx >= 0) ? (gx >> 6) : 0;   // classes xc and xc+2
    u64 wxd[2][IN_];                  // dup x-weights: 156 regs, X threads only
    u64 xb2[2] = {zero2, zero2};
    if (!isAB) {
        #pragma unroll
        for (int j = 0; j < IN_; j++) {
            float v0 = W_ih[((xc    )*64 + xu)*IN_ + j];
            float v1 = W_ih[((xc + 2)*64 + xu)*IN_ + j];
            wxd[0][j] = pack2(v0, v0);
            wxd[1][j] = pack2(v1, v1);
        }
        float b0 = b_ih[(xc    )*64 + xu] + b_hh[(xc    )*64 + xu];
        float b1 = b_ih[(xc + 2)*64 + xu] + b_hh[(xc + 2)*64 + xu];
        xb2[0] = pack2(b0, b0);
        xb2[1] = pack2(b1, b1);
    }
    // C1 identity (gx<96): (output o1, k-half kh)
    const int o1 = (gx >= 0) ? (gx % 48) : 0;
    const int kh = (gx >= 0) ? (gx / 48) : 0;   // 0..1 valid when gx<96
    u64 cb2 = zero2;
    if (!isAB && gx < 96 && kh == 0) { float b = b_out[o1]; cb2 = pack2(b, b); }

    // ======== prologue ========
    if (tid < H_) {
        #pragma unroll
        for (int r = 0; r < 4; r++) {
            hsT4[0][tid][r] = 0.0f;
            hsT4[1][tid][r] = 0.0f;
        }
    }
    for (int idx = tid; idx < H_*OUT_; idx += NTHR) {
        int k = idx / OUT_, o = idx % OUT_;
        woS[k][o] = W_out[o*H_ + k];
    }
    __syncthreads();
    if (stg) {   // stage x(0), x(1) transposed
        xs4[0][si][sr] = x[((size_t)(row0 + sr) * T_    ) * IN_ + si];
        xs4[1][si][sr] = x[((size_t)(row0 + sr) * T_ + 1) * IN_ + si];
    }
    __syncthreads();
    // X: xg(0) from xs4[0] -> xgS[0]
    if (!isAB) {
        u64 aA01 = xb2[0], aA23 = xb2[0], aB01 = xb2[1], aB23 = xb2[1];
        const ulonglong2* xp = (const ulonglong2*)xs4[0];
        #pragma unroll
        for (int k = 0; k < IN_; k++) {
            ulonglong2 q = xp[k];
            aA01 = fma2(wxd[0][k], q.x, aA01);
            aA23 = fma2(wxd[0][k], q.y, aA23);
            aB01 = fma2(wxd[1][k], q.x, aB01);
            aB23 = fma2(wxd[1][k], q.y, aB23);
        }
        xgS[0][xc    ][0][xu] = aA01;
        xgS[0][xc    ][1][xu] = aA23;
        xgS[0][xc + 2][0][xu] = aB01;
        xgS[0][xc + 2][1][xu] = aB23;
    }
    __syncthreads();

    float xnext = 0.0f;
    for (int t = 0; t < T_; t++) {
        const int wb = t & 1;        // B writes hsT4[wb]; C1 writes pc[wb]
        const int hb = wb ^ 1;       // A + C1 read hsT4[hb]; C2 reads pc[hb]
        const bool pf = stg && (t + 2 < T_);
        if (pf) xnext = x[((size_t)(row0 + sr) * T_ + (t + 2)) * IN_ + si];

        if (isAB) {
            // ---- Phase A: h-part only -> pq ----
            u64 a01[4] = {zero2, zero2, zero2, zero2};
            u64 a23[4] = {zero2, zero2, zero2, zero2};
            const ulonglong2* hp = (const ulonglong2*)hsT4[hb] + ks*16;
            #pragma unroll
            for (int j = 0; j < 16; j++) {
                ulonglong2 q = hp[j];        // .x=(r0,r1) .y=(r2,r3)
                #pragma unroll
                for (int c = 0; c < 4; c++) {
                    a01[c] = fma2(wA[c][j], q.x, a01[c]);
                    a23[c] = fma2(wA[c][j], q.y, a23[c]);
                }
            }
            #pragma unroll
            for (int c = 0; c < 4; c++) {
                float v0, v1;
                unpack2(a01[c], v0, v1);
                pq[ks][c][0][ua] = v0; pq[ks][c][1][ua] = v1;
                unpack2(a23[c], v0, v1);
                pq[ks][c][2][ua] = v0; pq[ks][c][3][ua] = v1;
            }
        } else if (t + 1 < T_) {
            // ---- Phase X: xg(t+1) from xs4[(t+1)&1] -> xgS[(t+1)&1] ----
            u64 aA01 = xb2[0], aA23 = xb2[0], aB01 = xb2[1], aB23 = xb2[1];
            const ulonglong2* xp = (const ulonglong2*)xs4[(t + 1) & 1];
            #pragma unroll
            for (int k = 0; k < IN_; k++) {
                ulonglong2 q = xp[k];
                aA01 = fma2(wxd[0][k], q.x, aA01);
                aA23 = fma2(wxd[0][k], q.y, aA23);
                aB01 = fma2(wxd[1][k], q.x, aB01);
                aB23 = fma2(wxd[1][k], q.y, aB23);
            }
            const int nb = (t + 1) & 1;
            xgS[nb][xc    ][0][xu] = aA01;
            xgS[nb][xc    ][1][xu] = aA23;
            xgS[nb][xc + 2][0][xu] = aB01;
            xgS[nb][xc + 2][1][xu] = aB23;
        }
        __syncthreads();   // bar1

        if (isAB) {
            // ---- C2: emit y(t-2) from pc[hb] (tid<48) ----
            if (tid < 48 && t >= 2) {
                u64 s01 = add2(pc[hb][0][0][o2], pc[hb][1][0][o2]);
                u64 s23 = add2(pc[hb][0][1][o2], pc[hb][1][1][o2]);
                float z0, z1, z2, z3;
                unpack2(s01, z0, z1);
                unpack2(s23, z2, z3);
                const size_t tb = (size_t)(t - 2) * OUT_ + o2;
                out[(size_t)(row0    ) * T_ * OUT_ + tb] = sigm(z0);
                out[(size_t)(row0 + 1) * T_ * OUT_ + tb] = sigm(z1);
                out[(size_t)(row0 + 2) * T_ * OUT_ + tb] = sigm(z2);
                out[(size_t)(row0 + 3) * T_ * OUT_ + tb] = sigm(z3);
            }
            // ---- Phase B: gates = pq sums + xg (from xgS[wb]) ----
            {
                float xg0 = ((const float*)&xgS[wb][0][rp][ub])[rl];
                float xg1 = ((const float*)&xgS[wb][1][rp][ub])[rl];
                float xg2 = ((const float*)&xgS[wb][2][rp][ub])[rl];
                float xg3 = ((const float*)&xgS[wb][3][rp][ub])[rl];
                float si_ = xg0 + ((pq[0][0][rb][ub] + pq[1][0][rb][ub])
                                 + (pq[2][0][rb][ub] + pq[3][0][rb][ub]));
                float sf_ = xg1 + ((pq[0][1][rb][ub] + pq[1][1][rb][ub])
                                 + (pq[2][1][rb][ub] + pq[3][1][rb][ub]));
                float sg_ = xg2 + ((pq[0][2][rb][ub] + pq[1][2][rb][ub])
                                 + (pq[2][2][rb][ub] + pq[3][2][rb][ub]));
                float so_ = xg3 + ((pq[0][3][rb][ub] + pq[1][3][rb][ub])
                                 + (pq[2][3][rb][ub] + pq[3][3][rb][ub]));
                float iv = sigm(si_), fv = sigm(sf_);
                float gv = tanh_(sg_), ov = sigm(so_);
                cst = fv * cst + iv * gv;
                hsT4[wb][ub][rb] = ov * tanh_(cst);
            }
            if (pf) xs4[wb][si][sr] = xnext;   // publish x(t+2) -> xs4[(t+2)&1]
        } else {
            // ---- C1: head(h(t-1)) partials from hsT4[hb] -> pc[wb] ----
            if (gx < 96 && t >= 1) {
                u64 a01 = cb2, a23 = cb2;
                const ulonglong2* hp = (const ulonglong2*)hsT4[hb] + kh*32;
                #pragma unroll
                for (int j = 0; j < 32; j++) {
                    ulonglong2 q = hp[j];
                    float wv = woS[kh*32 + j][o1];
                    u64 w2 = pack2(wv, wv);
                    a01 = fma2(w2, q.x, a01);
                    a23 = fma2(w2, q.y, a23);
                }
                pc[wb][kh][0][o1] = a01;
                pc[wb][kh][1][o1] = a23;
            }
        }
        __syncthreads();   // bar2
    }

    // ---- epilogue: head of h(999) -> pc[0], then emit y(998), y(999) ----
    if (!isAB && gx < 96) {
        u64 a01 = cb2, a23 = cb2;
        const ulonglong2* hp = (const ulonglong2*)hsT4[1] + kh*32;
        #pragma unroll
        for (int j = 0; j < 32; j++) {
            ulonglong2 q = hp[j];
            float wv = woS[kh*32 + j][o1];
            u64 w2 = pack2(wv, wv);
            a01 = fma2(w2, q.x, a01);
            a23 = fma2(w2, q.y, a23);
        }
        pc[0][kh][0][o1] = a01;
        pc[0][kh][1][o1] = a23;
    }
    __syncthreads();
    if (tid < 48) {
        #pragma unroll
        for (int e = 0; e < 2; e++) {   // e=0: y(998) from pc[1]; e=1: y(999) from pc[0]
            const int pb = 1 - e;
            const int ts = 998 + e;
            u64 s01 = add2(pc[pb][0][0][o2], pc[pb][1][0][o2]);
            u64 s23 = add2(pc[pb][0][1][o2], pc[pb][1][1][o2]);
            float z0, z1, z2, z3;
            unpack2(s01, z0, z1);
            unpack2(s23, z2, z3);
            const size_t tb = (size_t)ts * OUT_ + o2;
            out[(size_t)(row0    ) * T_ * OUT_ + tb] = sigm(z0);
            out[(size_t)(row0 + 1) * T_ * OUT_ + tb] = sigm(z1);
            out[(size_t)(row0 + 2) * T_ * OUT_ + tb] = sigm(z2);
            out[(size_t)(row0 + 3) * T_ * OUT_ + tb] = sigm(z3);
        }
    }
}

extern "C" void kernel_launch(void* const* d_in, const int* in_sizes, int n_in,
                              void* d_out, int out_size)
{
    (void)in_sizes; (void)n_in; (void)out_size;
    const float* x     = (const float*)d_in[0];
    const float* W_ih  = (const float*)d_in[1];
    const float* W_hh  = (const float*)d_in[2];
    const float* b_ih  = (const float*)d_in[3];
    const float* b_hh  = (const float*)d_in[4];
    const float* W_out = (const float*)d_in[5];
    const float* b_out = (const float*)d_in[6];
    float* out = (float*)d_out;

    lstm_fused<<<CTAS, NTHR>>>(x, W_ih, W_hh, b_ih, b_hh, W_out, b_out, out);
}

// round 16
// speedup vs baseline: 1.7385x; 1.4647x over previous
#include <cuda_runtime.h>

// LSTM: B=512, T=1000, IN=39, H=64 (4H=256 gates), OUT=48.
// R15 = R12 with the output head C1 HOISTED from the B-window into the
// A-window. C1 only needs h(t-1) (ready since bar2 of t-1) and constants,
// so it overlaps the FMA-pipelined A-window (+64 FFMA2-issue cyc/SMSP)
// instead of stretching the latency-exposed B-window (~1000 -> ~300 cyc).
// R14's lesson applied: no new warps, no new registers — same threads,
// same code, relocated across the barrier.

#define B_    512
#define T_    1000
#define IN_   39
#define H_    64
#define G_    256
#define OUT_  48
#define ROWS  4
#define CTAS  (B_/ROWS)   // 128
#define KXP   48          // x scalars padded 39->48 (24 pairs, 6 pairs/quarter)

typedef unsigned long long u64;

__device__ __forceinline__ u64 fma2(u64 a, u64 b, u64 c) {
    u64 d;
    asm("fma.rn.f32x2 %0, %1, %2, %3;" : "=l"(d) : "l"(a), "l"(b), "l"(c));
    return d;
}
__device__ __forceinline__ u64 add2(u64 a, u64 b) {
    u64 d;
    asm("add.rn.f32x2 %0, %1, %2;" : "=l"(d) : "l"(a), "l"(b));
    return d;
}
__device__ __forceinline__ u64 pack2(float lo, float hi) {
    u64 d;
    asm("mov.b64 %0, {%1, %2};" : "=l"(d) : "f"(lo), "f"(hi));
    return d;
}
__device__ __forceinline__ void unpack2(u64 v, float &lo, float &hi) {
    asm("mov.b64 {%0, %1}, %2;" : "=f"(lo), "=f"(hi) : "l"(v));
}
__device__ __forceinline__ float sigm(float x) {
    return __fdividef(1.0f, 1.0f + __expf(-x));
}
__device__ __forceinline__ float tanh_(float x) {
    float e = __expf(2.0f * x);
    return 1.0f - __fdividef(2.0f, e + 1.0f);
}

__global__ void __launch_bounds__(256, 1)
lstm_fused(const float* __restrict__ x,
           const float* __restrict__ W_ih,
           const float* __restrict__ W_hh,
           const float* __restrict__ b_ih,
           const float* __restrict__ b_hh,
           const float* __restrict__ W_out,
           const float* __restrict__ b_out,
           float* __restrict__ out)
{
    __shared__ __align__(16) float hsT4[2][H_][4];   // dbl-buf rowpack h, 2KB
    __shared__ __align__(16) float pq[4][4][4][H_];  // [ks][class][row][u] 16KB
    __shared__ __align__(16) u64   pc[2][4][2][OUT_];// dbl-buf head partials 6KB
    __shared__ __align__(16) float woS[H_][OUT_];    // W_out un-dup'd 12KB
    __shared__ __align__(16) float xs[2][ROWS][KXP]; // x tile dbl-buf 1.5KB

    const int tid  = threadIdx.x;
    const int row0 = blockIdx.x * ROWS;

    // ---- Phase A identity: (unit ua, k-quarter ks); gates = ua + 64c ----
    const int ua = tid & 63;
    const int ks = tid >> 6;                 // 0..3
    u64 wA[4][16];                           // h-part dup (w,w): 128 regs
    #pragma unroll
    for (int c = 0; c < 4; c++)
        #pragma unroll
        for (int j = 0; j < 16; j++) {
            float v = W_hh[(c*64 + ua)*H_ + ks*16 + j];
            wA[c][j] = pack2(v, v);
        }
    u64 wx[4][6];                            // x-part pair weights: 48 regs
    #pragma unroll
    for (int c = 0; c < 4; c++)
        #pragma unroll
        for (int j = 0; j < 6; j++) {
            int k0 = (ks*6 + j)*2, k1 = k0 + 1;
            float lo = (k0 < IN_) ? W_ih[(c*64 + ua)*IN_ + k0] : 0.0f;
            float hi = (k1 < IN_) ? W_ih[(c*64 + ua)*IN_ + k1] : 0.0f;
            wx[c][j] = pack2(lo, hi);
        }
    const u64 zero2 = pack2(0.0f, 0.0f);
    u64 bias2c[4];                           // (b,0): ks==0 threads only
    #pragma unroll
    for (int c = 0; c < 4; c++) {
        float b = (ks == 0) ? (b_ih[c*64 + ua] + b_hh[c*64 + ua]) : 0.0f;
        bias2c[c] = pack2(b, 0.0f);
    }

    // ---- Phase B identity: (unit ub, row rb) ----
    const int ub = tid & 63;
    const int rb = tid >> 6;
    float cst = 0.0f;

    // ---- stager identity (tid<156): x element (sr, si) ----
    const bool stg = (tid < ROWS*IN_);
    const int  sr  = stg ? (tid / IN_) : 0;
    const int  si  = stg ? (tid % IN_) : 0;

    // ---- head C1 identity (tid>=64): (output o1, k-quarter kc) ----
    const int i1 = tid - 64;                 // 0..191 when tid>=64
    const int o1 = (i1 >= 0) ? (i1 % 48) : 0;
    const int kc = (i1 >= 0) ? (i1 / 48) : 0;
    u64 cb2 = zero2;
    if (i1 >= 0 && kc == 0) { float b = b_out[o1]; cb2 = pack2(b, b); }
    // ---- head C2 identity (tid<48): output o2, all 4 rows ----
    const int o2 = tid;

    // ---- prologue ----
    for (int idx = tid; idx < 2*ROWS*KXP; idx += 256)
        ((float*)xs)[idx] = 0.0f;
    if (tid < H_) {
        #pragma unroll
        for (int r = 0; r < 4; r++) {
            hsT4[0][tid][r] = 0.0f;
            hsT4[1][tid][r] = 0.0f;
        }
    }
    for (int idx = tid; idx < H_*OUT_; idx += 256) {
        int k = idx / OUT_, o = idx % OUT_;
        woS[k][o] = W_out[o*H_ + k];
    }
    __syncthreads();
    if (stg) xs[0][sr][si] = x[((size_t)(row0 + sr) * T_) * IN_ + si];
    __syncthreads();

    float xnext = 0.0f;
    for (int t = 0; t < T_; t++) {
        const int wb = t & 1;        // B writes hsT4[wb]; C1 writes pc[wb]
        const int hb = wb ^ 1;       // A + C1 read hsT4[hb]; C2 reads pc[hb]
        const bool pf = stg && (t + 1 < T_);
        if (pf) xnext = x[((size_t)(row0 + sr) * T_ + (t + 1)) * IN_ + si];

        // ==== A-window: A(t) | C1(t-1) overlapped ====

        // ---- Phase A: gates(t) = W_hh·h(t-1) + W_ih·x(t) + b, into pq ----
        {
            u64 a01[4] = {zero2, zero2, zero2, zero2};
            u64 a23[4] = {zero2, zero2, zero2, zero2};
            const ulonglong2* hp = (const ulonglong2*)hsT4[hb] + ks*16;
            #pragma unroll
            for (int j = 0; j < 16; j++) {
                ulonglong2 q = hp[j];        // .x=(r0,r1) .y=(r2,r3)
                #pragma unroll
                for (int c = 0; c < 4; c++) {
                    a01[c] = fma2(wA[c][j], q.x, a01[c]);
                    a23[c] = fma2(wA[c][j], q.y, a23[c]);
                }
            }
            float hv[4][4];
            #pragma unroll
            for (int c = 0; c < 4; c++) {
                unpack2(a01[c], hv[c][0], hv[c][1]);
                unpack2(a23[c], hv[c][2], hv[c][3]);
            }
            #pragma unroll
            for (int r = 0; r < 4; r++) {
                u64 axr[4];
                #pragma unroll
                for (int c = 0; c < 4; c++) axr[c] = bias2c[c];
                const ulonglong2* xp = (const ulonglong2*)xs[wb][r] + ks*3;
                #pragma unroll
                for (int m = 0; m < 3; m++) {
                    ulonglong2 q = xp[m];
                    #pragma unroll
                    for (int c = 0; c < 4; c++) {
                        axr[c] = fma2(wx[c][2*m    ], q.x, axr[c]);
                        axr[c] = fma2(wx[c][2*m + 1], q.y, axr[c]);
                    }
                }
                #pragma unroll
                for (int c = 0; c < 4; c++) {
                    float e, f; unpack2(axr[c], e, f);
                    pq[ks][c][r][ua] = hv[c][r] + (e + f);
                }
            }
        }

        // ---- head C1 (hoisted): partials of head(h(t-1)) from hsT4[hb] ----
        if (i1 >= 0 && t >= 1) {
            u64 a01 = cb2, a23 = cb2;
            const ulonglong2* hp = (const ulonglong2*)hsT4[hb] + kc*16;
            #pragma unroll
            for (int j = 0; j < 16; j++) {
                ulonglong2 q = hp[j];
                float wv = woS[kc*16 + j][o1];
                u64 w2 = pack2(wv, wv);
                a01 = fma2(w2, q.x, a01);
                a23 = fma2(w2, q.y, a23);
            }
            pc[wb][kc][0][o1] = a01;
            pc[wb][kc][1][o1] = a23;
        }
        __syncthreads();   // bar1

        // ==== B-window: C2(t-2) | B(t) | x-stage ====

        // ---- head C2: emit y(t-2) from pc[hb] (tid<48) ----
        if (tid < 48 && t >= 2) {
            u64 s01 = add2(add2(pc[hb][0][0][o2], pc[hb][1][0][o2]),
                           add2(pc[hb][2][0][o2], pc[hb][3][0][o2]));
            u64 s23 = add2(add2(pc[hb][0][1][o2], pc[hb][1][1][o2]),
                           add2(pc[hb][2][1][o2], pc[hb][3][1][o2]));
            float z0, z1, z2, z3;
            unpack2(s01, z0, z1);
            unpack2(s23, z2, z3);
            const size_t tb = (size_t)(t - 2) * OUT_ + o2;
            out[(size_t)(row0    ) * T_ * OUT_ + tb] = sigm(z0);
            out[(size_t)(row0 + 1) * T_ * OUT_ + tb] = sigm(z1);
            out[(size_t)(row0 + 2) * T_ * OUT_ + tb] = sigm(z2);
            out[(size_t)(row0 + 3) * T_ * OUT_ + tb] = sigm(z3);
        }

        // ---- Phase B: sum partials, activations, write h(t) -> hsT4[wb] ----
        {
            float si_ = (pq[0][0][rb][ub] + pq[1][0][rb][ub])
                      + (pq[2][0][rb][ub] + pq[3][0][rb][ub]);
            float sf_ = (pq[0][1][rb][ub] + pq[1][1][rb][ub])
                      + (pq[2][1][rb][ub] + pq[3][1][rb][ub]);
            float sg_ = (pq[0][2][rb][ub] + pq[1][2][rb][ub])
                      + (pq[2][2][rb][ub] + pq[3][2][rb][ub]);
            float so_ = (pq[0][3][rb][ub] + pq[1][3][rb][ub])
                      + (pq[2][3][rb][ub] + pq[3][3][rb][ub]);
            float iv = sigm(si_), fv = sigm(sf_);
            float gv = tanh_(sg_), ov = sigm(so_);
            cst = fv * cst + iv * gv;
            hsT4[wb][ub][rb] = ov * tanh_(cst);
        }

        if (pf) xs[wb ^ 1][sr][si] = xnext;   // publish x(t+1)
        __syncthreads();   // bar2
    }

    // ---- epilogue: head of h(999), then emit y(998), y(999) ----
    // loop ended at bar2 of t=999; h(999) is in hsT4[1], pc[1] holds head(h(998)).
    if (i1 >= 0) {
        u64 a01 = cb2, a23 = cb2;
        const ulonglong2* hp = (const ulonglong2*)hsT4[1] + kc*16;
        #pragma unroll
        for (int j = 0; j < 16; j++) {
            ulonglong2 q = hp[j];
            float wv = woS[kc*16 + j][o1];
            u64 w2 = pack2(wv, wv);
            a01 = fma2(w2, q.x, a01);
            a23 = fma2(w2, q.y, a23);
        }
        pc[0][kc][0][o1] = a01;
        pc[0][kc][1][o1] = a23;
    }
    __syncthreads();
    if (tid < 48) {
        #pragma unroll
        for (int e = 0; e < 2; e++) {   // e=0: y(998) from pc[1]; e=1: y(999) from pc[0]
            const int pb = 1 - e;
            const int ts = 998 + e;
            u64 s01 = add2(add2(pc[pb][0][0][o2], pc[pb][1][0][o2]),
                           add2(pc[pb][2][0][o2], pc[pb][3][0][o2]));
            u64 s23 = add2(add2(pc[pb][0][1][o2], pc[pb][1][1][o2]),
                           add2(pc[pb][2][1][o2], pc[pb][3][1][o2]));
            float z0, z1, z2, z3;
            unpack2(s01, z0, z1);
            unpack2(s23, z2, z3);
            const size_t tb = (size_t)ts * OUT_ + o2;
            out[(size_t)(row0    ) * T_ * OUT_ + tb] = sigm(z0);
            out[(size_t)(row0 + 1) * T_ * OUT_ + tb] = sigm(z1);
            out[(size_t)(row0 + 2) * T_ * OUT_ + tb] = sigm(z2);
            out[(size_t)(row0 + 3) * T_ * OUT_ + tb] = sigm(z3);
        }
    }
}

extern "C" void kernel_launch(void* const* d_in, const int* in_sizes, int n_in,
                              void* d_out, int out_size)
{
    (void)in_sizes; (void)n_in; (void)out_size;
    const float* x     = (const float*)d_in[0];
    const float* W_ih  = (const float*)d_in[1];
    const float* W_hh  = (const float*)d_in[2];
    const float* b_ih  = (const float*)d_in[3];
    const float* b_hh  = (const float*)d_in[4];
    const float* W_out = (const float*)d_in[5];
    const float* b_out = (const float*)d_in[6];
    float* out = (float*)d_out;

    lstm_fused<<<CTAS, 256>>>(x, W_ih, W_hh, b_ih, b_hh, W_out, b_out, out);
}